// round 1
// baseline (speedup 1.0000x reference)
#include <cuda_runtime.h>
#include <math.h>

// Problem constants
#define NB     64
#define DIM    64
#define HH     32
#define WW     32
#define HW     1024          // HH*WW
#define NTOK   65536         // NB*HW
#define KCODES 1024
#define KC     128           // codes per smem chunk
#define ZQ_ELEMS 4194304     // NB*DIM*HW

// Scratch (device globals; no allocation allowed)
__device__ __align__(16) float g_cbT[DIM * KCODES];  // transposed codebook [c][k]
__device__ float g_cnorm[KCODES];
__device__ int   g_idx[NTOK];
__device__ float g_losssum;
__device__ int   g_hist[KCODES];

// ---------------------------------------------------------------------------
// Prep: transpose codebook, compute ||c_k||^2, zero accumulators
// ---------------------------------------------------------------------------
__global__ void prep_kernel(const float* __restrict__ cb) {
    int k = blockIdx.x * blockDim.x + threadIdx.x;
    if (k >= KCODES) return;
    float s = 0.f;
#pragma unroll
    for (int c = 0; c < DIM; ++c) {
        float v = cb[k * DIM + c];
        s = fmaf(v, v, s);
        g_cbT[c * KCODES + k] = v;   // coalesced across k per c
    }
    g_cnorm[k] = s;
    g_hist[k]  = 0;
    if (k == 0) g_losssum = 0.f;
}

// ---------------------------------------------------------------------------
// Argmin: per-thread token, codebook streamed via smem, 8 acc chains
// score(k) = ||c_k||^2 - 2 * z . c_k   (||z||^2 dropped: constant per token)
// ---------------------------------------------------------------------------
__global__ void __launch_bounds__(128) argmin_kernel(const float* __restrict__ z) {
    __shared__ __align__(16) float sm_cb[DIM * KC];  // [c][KC]  32 KB
    __shared__ float sm_cn[KC];

    const int tid = threadIdx.x;
    const int n   = blockIdx.x * 128 + tid;
    const int b   = n >> 10;
    const int hw  = n & (HW - 1);
    const float* zp = z + b * (DIM * HW) + hw;

    float zr[DIM];
#pragma unroll
    for (int c = 0; c < DIM; ++c) zr[c] = zp[c << 10];  // coalesced across warp

    float best = 3.4e38f;
    int   bidx = 0;

    for (int kc = 0; kc < KCODES; kc += KC) {
        __syncthreads();  // previous chunk fully consumed
        // Load chunk: DIM*KC floats = 2048 float4, 16 per thread, coalesced
#pragma unroll
        for (int i = 0; i < (DIM * KC / 4) / 128; ++i) {
            int t = tid + i * 128;
            int c = t >> 5;          // KC/4 = 32 float4 per row
            int j = t & 31;
            ((float4*)sm_cb)[c * (KC / 4) + j] =
                ((const float4*)(g_cbT + c * KCODES + kc))[j];
        }
        sm_cn[tid] = g_cnorm[kc + tid];
        __syncthreads();

        for (int k8 = 0; k8 < KC; k8 += 8) {
            float a0 = 0.f, a1 = 0.f, a2 = 0.f, a3 = 0.f;
            float a4 = 0.f, a5 = 0.f, a6 = 0.f, a7 = 0.f;
#pragma unroll
            for (int c = 0; c < DIM; ++c) {
                float4 c0 = *((const float4*)(sm_cb + c * KC + k8));       // broadcast
                float4 c1 = *((const float4*)(sm_cb + c * KC + k8 + 4));   // broadcast
                float zc = zr[c];
                a0 = fmaf(zc, c0.x, a0);
                a1 = fmaf(zc, c0.y, a1);
                a2 = fmaf(zc, c0.z, a2);
                a3 = fmaf(zc, c0.w, a3);
                a4 = fmaf(zc, c1.x, a4);
                a5 = fmaf(zc, c1.y, a5);
                a6 = fmaf(zc, c1.z, a6);
                a7 = fmaf(zc, c1.w, a7);
            }
            float s;
            // strict < and ascending k order -> first-occurrence tie behavior
            s = fmaf(-2.f, a0, sm_cn[k8 + 0]); if (s < best) { best = s; bidx = kc + k8 + 0; }
            s = fmaf(-2.f, a1, sm_cn[k8 + 1]); if (s < best) { best = s; bidx = kc + k8 + 1; }
            s = fmaf(-2.f, a2, sm_cn[k8 + 2]); if (s < best) { best = s; bidx = kc + k8 + 2; }
            s = fmaf(-2.f, a3, sm_cn[k8 + 3]); if (s < best) { best = s; bidx = kc + k8 + 3; }
            s = fmaf(-2.f, a4, sm_cn[k8 + 4]); if (s < best) { best = s; bidx = kc + k8 + 4; }
            s = fmaf(-2.f, a5, sm_cn[k8 + 5]); if (s < best) { best = s; bidx = kc + k8 + 5; }
            s = fmaf(-2.f, a6, sm_cn[k8 + 6]); if (s < best) { best = s; bidx = kc + k8 + 6; }
            s = fmaf(-2.f, a7, sm_cn[k8 + 7]); if (s < best) { best = s; bidx = kc + k8 + 7; }
        }
    }
    g_idx[n] = bidx;
}

// ---------------------------------------------------------------------------
// Epilogue: gather codes -> NCHW output, accumulate (z_q - z)^2, histogram
// Note: z_q_st == z_q numerically; loss == 1.25 * mean((z_q - z)^2)
// ---------------------------------------------------------------------------
__global__ void __launch_bounds__(256) epilogue_kernel(const float* __restrict__ z,
                                                       const float* __restrict__ cb,
                                                       float* __restrict__ out) {
    const int b   = blockIdx.x >> 2;
    const int hw  = ((blockIdx.x & 3) << 8) | threadIdx.x;
    const int n   = (b << 10) | hw;
    const int idx = g_idx[n];
    atomicAdd(&g_hist[idx], 1);                 // each token exactly once
    const float* cbr = cb + idx * DIM;
    const int base = b * (DIM * HW) + hw;

    float acc = 0.f;
#pragma unroll
    for (int c = 0; c < DIM; ++c) {
        float q  = __ldg(cbr + c);              // L1/L2-resident gather
        float zv = z[base + (c << 10)];         // coalesced
        float d  = q - zv;
        acc = fmaf(d, d, acc);
        out[base + (c << 10)] = q;              // coalesced NCHW write
    }
    // deterministic in-block tree reduction
#pragma unroll
    for (int o = 16; o > 0; o >>= 1)
        acc += __shfl_down_sync(0xffffffffu, acc, o);
    __shared__ float red[8];
    if ((threadIdx.x & 31) == 0) red[threadIdx.x >> 5] = acc;
    __syncthreads();
    if (threadIdx.x == 0) {
        float s = 0.f;
#pragma unroll
        for (int w = 0; w < 8; ++w) s += red[w];
        atomicAdd(&g_losssum, s);
    }
}

// ---------------------------------------------------------------------------
// Finalize: perplexity from histogram + loss scalar
// ---------------------------------------------------------------------------
__global__ void finalize_kernel(const int* __restrict__ flg,
                                float* __restrict__ out, int write_scalars) {
    const int k = threadIdx.x;  // 1024 threads
    float e = (float)g_hist[k] * (1.f / (float)NTOK);
    float t = e * logf(e + 1e-10f);
#pragma unroll
    for (int o = 16; o > 0; o >>= 1)
        t += __shfl_down_sync(0xffffffffu, t, o);
    __shared__ float red[32];
    if ((k & 31) == 0) red[k >> 5] = t;
    __syncthreads();
    if (k < 32) {
        float v = red[k];
#pragma unroll
        for (int o = 16; o > 0; o >>= 1)
            v += __shfl_down_sync(0xffffffffu, v, o);
        if (k == 0 && write_scalars) {
            int fbits = *flg;                   // nonzero bits == true (int or float 1)
            float loss = (fbits != 0)
                       ? 1.25f * g_losssum * (1.f / (float)ZQ_ELEMS)
                       : 0.f;
            out[ZQ_ELEMS]     = loss;
            out[ZQ_ELEMS + 1] = expf(-v);
        }
    }
}

// ---------------------------------------------------------------------------
extern "C" void kernel_launch(void* const* d_in, const int* in_sizes, int n_in,
                              void* d_out, int out_size) {
    const float* z   = (const float*)d_in[0];   // (64,64,32,32) f32
    const float* cb  = (const float*)d_in[1];   // (1024,64) f32
    const int*   flg = (const int*)d_in[3];     // scalar
    float* out = (float*)d_out;

    prep_kernel<<<8, 128>>>(cb);
    argmin_kernel<<<NTOK / 128, 128>>>(z);
    epilogue_kernel<<<256, 256>>>(z, cb, out);
    finalize_kernel<<<1, 1024>>>(flg, out, out_size >= ZQ_ELEMS + 2 ? 1 : 0);
}

// round 2
// speedup vs baseline: 1.0474x; 1.0474x over previous
#include <cuda_runtime.h>
#include <math.h>

// Problem constants
#define NB     64
#define DIM    64
#define HH     32
#define WW     32
#define HW     1024          // HH*WW
#define NTOK   65536         // NB*HW
#define KCODES 1024
#define KC     128           // codes per smem chunk
#define ZQ_ELEMS 4194304     // NB*DIM*HW

// Scratch (device globals; no allocation allowed)
__device__ __align__(16) float g_cbT[DIM * KCODES];  // transposed codebook [c][k]
__device__ float g_cnorm[KCODES];
__device__ int   g_idx[NTOK];
__device__ float g_losssum;
__device__ int   g_hist[KCODES];

// ---------------------------------------------------------------------------
// Packed fp32x2 helpers (sm_103a FFMA2 — ptxas never auto-fuses, must use PTX)
// ---------------------------------------------------------------------------
__device__ __forceinline__ void fma2(unsigned long long& acc,
                                     unsigned long long a,
                                     unsigned long long b) {
    asm("fma.rn.f32x2 %0, %1, %2, %0;" : "+l"(acc) : "l"(a), "l"(b));
}
__device__ __forceinline__ unsigned long long pack2(float x) {
    unsigned long long r;
    unsigned int xi = __float_as_uint(x);
    asm("mov.b64 %0, {%1, %1};" : "=l"(r) : "r"(xi));
    return r;
}
__device__ __forceinline__ float2 unpack2(unsigned long long v) {
    float2 f;
    unsigned int lo, hi;
    asm("mov.b64 {%0, %1}, %2;" : "=r"(lo), "=r"(hi) : "l"(v));
    f.x = __uint_as_float(lo);
    f.y = __uint_as_float(hi);
    return f;
}

// ---------------------------------------------------------------------------
// Prep: transpose codebook, compute ||c_k||^2, zero accumulators
// ---------------------------------------------------------------------------
__global__ void prep_kernel(const float* __restrict__ cb) {
    int k = blockIdx.x * blockDim.x + threadIdx.x;
    if (k >= KCODES) return;
    float s = 0.f;
#pragma unroll
    for (int c = 0; c < DIM; ++c) {
        float v = cb[k * DIM + c];
        s = fmaf(v, v, s);
        g_cbT[c * KCODES + k] = v;   // coalesced across k per c
    }
    g_cnorm[k] = s;
    g_hist[k]  = 0;
    if (k == 0) g_losssum = 0.f;
}

// ---------------------------------------------------------------------------
// Argmin: per-thread token; codebook streamed via smem; 16 codes per c-step
// via 8 packed f32x2 accumulator chains (FFMA2 = 2 MAC/issue).
// score(k) = ||c_k||^2 - 2 * z . c_k   (||z||^2 dropped: constant per token)
// ---------------------------------------------------------------------------
__global__ void __launch_bounds__(128) argmin_kernel(const float* __restrict__ z) {
    __shared__ __align__(16) float sm_cb[DIM * KC];  // [c][KC]  32 KB
    __shared__ float sm_cn[KC];

    const int tid = threadIdx.x;
    const int n   = blockIdx.x * 128 + tid;
    const int b   = n >> 10;
    const int hw  = n & (HW - 1);
    const float* zp = z + b * (DIM * HW) + hw;

    float zr[DIM];
#pragma unroll
    for (int c = 0; c < DIM; ++c) zr[c] = zp[c << 10];  // coalesced across warp

    float best = 3.4e38f;
    int   bidx = 0;

    for (int kc = 0; kc < KCODES; kc += KC) {
        __syncthreads();  // previous chunk fully consumed
        // Load chunk: DIM*KC floats = 2048 float4, 16 per thread, coalesced
#pragma unroll
        for (int i = 0; i < (DIM * KC / 4) / 128; ++i) {
            int t = tid + i * 128;
            int c = t >> 5;          // KC/4 = 32 float4 per row
            int j = t & 31;
            ((float4*)sm_cb)[c * (KC / 4) + j] =
                ((const float4*)(g_cbT + c * KCODES + kc))[j];
        }
        sm_cn[tid] = g_cnorm[kc + tid];
        __syncthreads();

        for (int k16 = 0; k16 < KC; k16 += 16) {
            unsigned long long a0 = 0ull, a1 = 0ull, a2 = 0ull, a3 = 0ull;
            unsigned long long a4 = 0ull, a5 = 0ull, a6 = 0ull, a7 = 0ull;
#pragma unroll
            for (int c = 0; c < DIM; ++c) {
                // 16 codes = 4 x LDS.128; each 64-bit lane is a packed f32x2 pair
                const ulonglong2* p =
                    (const ulonglong2*)(sm_cb + c * KC + k16);
                ulonglong2 q0 = p[0];
                ulonglong2 q1 = p[1];
                ulonglong2 q2 = p[2];
                ulonglong2 q3 = p[3];
                unsigned long long zz = pack2(zr[c]);
                fma2(a0, zz, q0.x);
                fma2(a1, zz, q0.y);
                fma2(a2, zz, q1.x);
                fma2(a3, zz, q1.y);
                fma2(a4, zz, q2.x);
                fma2(a5, zz, q2.y);
                fma2(a6, zz, q3.x);
                fma2(a7, zz, q3.y);
            }
            // Scores + argmin (strict <, ascending k -> first-occurrence ties)
            float2 f;
            float s;
            f = unpack2(a0);
            s = fmaf(-2.f, f.x, sm_cn[k16 +  0]); if (s < best) { best = s; bidx = kc + k16 +  0; }
            s = fmaf(-2.f, f.y, sm_cn[k16 +  1]); if (s < best) { best = s; bidx = kc + k16 +  1; }
            f = unpack2(a1);
            s = fmaf(-2.f, f.x, sm_cn[k16 +  2]); if (s < best) { best = s; bidx = kc + k16 +  2; }
            s = fmaf(-2.f, f.y, sm_cn[k16 +  3]); if (s < best) { best = s; bidx = kc + k16 +  3; }
            f = unpack2(a2);
            s = fmaf(-2.f, f.x, sm_cn[k16 +  4]); if (s < best) { best = s; bidx = kc + k16 +  4; }
            s = fmaf(-2.f, f.y, sm_cn[k16 +  5]); if (s < best) { best = s; bidx = kc + k16 +  5; }
            f = unpack2(a3);
            s = fmaf(-2.f, f.x, sm_cn[k16 +  6]); if (s < best) { best = s; bidx = kc + k16 +  6; }
            s = fmaf(-2.f, f.y, sm_cn[k16 +  7]); if (s < best) { best = s; bidx = kc + k16 +  7; }
            f = unpack2(a4);
            s = fmaf(-2.f, f.x, sm_cn[k16 +  8]); if (s < best) { best = s; bidx = kc + k16 +  8; }
            s = fmaf(-2.f, f.y, sm_cn[k16 +  9]); if (s < best) { best = s; bidx = kc + k16 +  9; }
            f = unpack2(a5);
            s = fmaf(-2.f, f.x, sm_cn[k16 + 10]); if (s < best) { best = s; bidx = kc + k16 + 10; }
            s = fmaf(-2.f, f.y, sm_cn[k16 + 11]); if (s < best) { best = s; bidx = kc + k16 + 11; }
            f = unpack2(a6);
            s = fmaf(-2.f, f.x, sm_cn[k16 + 12]); if (s < best) { best = s; bidx = kc + k16 + 12; }
            s = fmaf(-2.f, f.y, sm_cn[k16 + 13]); if (s < best) { best = s; bidx = kc + k16 + 13; }
            f = unpack2(a7);
            s = fmaf(-2.f, f.x, sm_cn[k16 + 14]); if (s < best) { best = s; bidx = kc + k16 + 14; }
            s = fmaf(-2.f, f.y, sm_cn[k16 + 15]); if (s < best) { best = s; bidx = kc + k16 + 15; }
        }
    }
    g_idx[n] = bidx;
}

// ---------------------------------------------------------------------------
// Epilogue: gather codes -> NCHW output, accumulate (z_q - z)^2, histogram
// Note: z_q_st == z_q numerically; loss == 1.25 * mean((z_q - z)^2)
// ---------------------------------------------------------------------------
__global__ void __launch_bounds__(256) epilogue_kernel(const float* __restrict__ z,
                                                       const float* __restrict__ cb,
                                                       float* __restrict__ out) {
    const int b   = blockIdx.x >> 2;
    const int hw  = ((blockIdx.x & 3) << 8) | threadIdx.x;
    const int n   = (b << 10) | hw;
    const int idx = g_idx[n];
    atomicAdd(&g_hist[idx], 1);                 // each token exactly once
    const float* cbr = cb + idx * DIM;
    const int base = b * (DIM * HW) + hw;

    float acc = 0.f;
#pragma unroll
    for (int c = 0; c < DIM; ++c) {
        float q  = __ldg(cbr + c);              // L1/L2-resident gather
        float zv = z[base + (c << 10)];         // coalesced
        float d  = q - zv;
        acc = fmaf(d, d, acc);
        out[base + (c << 10)] = q;              // coalesced NCHW write
    }
    // deterministic in-block tree reduction
#pragma unroll
    for (int o = 16; o > 0; o >>= 1)
        acc += __shfl_down_sync(0xffffffffu, acc, o);
    __shared__ float red[8];
    if ((threadIdx.x & 31) == 0) red[threadIdx.x >> 5] = acc;
    __syncthreads();
    if (threadIdx.x == 0) {
        float s = 0.f;
#pragma unroll
        for (int w = 0; w < 8; ++w) s += red[w];
        atomicAdd(&g_losssum, s);
    }
}

// ---------------------------------------------------------------------------
// Finalize: perplexity from histogram + loss scalar
// ---------------------------------------------------------------------------
__global__ void finalize_kernel(const int* __restrict__ flg,
                                float* __restrict__ out, int write_scalars) {
    const int k = threadIdx.x;  // 1024 threads
    float e = (float)g_hist[k] * (1.f / (float)NTOK);
    float t = e * logf(e + 1e-10f);
#pragma unroll
    for (int o = 16; o > 0; o >>= 1)
        t += __shfl_down_sync(0xffffffffu, t, o);
    __shared__ float red[32];
    if ((k & 31) == 0) red[k >> 5] = t;
    __syncthreads();
    if (k < 32) {
        float v = red[k];
#pragma unroll
        for (int o = 16; o > 0; o >>= 1)
            v += __shfl_down_sync(0xffffffffu, v, o);
        if (k == 0 && write_scalars) {
            int fbits = *flg;                   // nonzero bits == true (int or float 1)
            float loss = (fbits != 0)
                       ? 1.25f * g_losssum * (1.f / (float)ZQ_ELEMS)
                       : 0.f;
            out[ZQ_ELEMS]     = loss;
            out[ZQ_ELEMS + 1] = expf(-v);
        }
    }
}

// ---------------------------------------------------------------------------
extern "C" void kernel_launch(void* const* d_in, const int* in_sizes, int n_in,
                              void* d_out, int out_size) {
    const float* z   = (const float*)d_in[0];   // (64,64,32,32) f32
    const float* cb  = (const float*)d_in[1];   // (1024,64) f32
    const int*   flg = (const int*)d_in[3];     // scalar
    float* out = (float*)d_out;

    prep_kernel<<<8, 128>>>(cb);
    argmin_kernel<<<NTOK / 128, 128>>>(z);
    epilogue_kernel<<<256, 256>>>(z, cb, out);
    finalize_kernel<<<1, 1024>>>(flg, out, out_size >= ZQ_ELEMS + 2 ? 1 : 0);
}

// round 6
// speedup vs baseline: 1.5462x; 1.4762x over previous
#include <cuda_runtime.h>
#include <cuda_bf16.h>
#include <math.h>
#include <stdint.h>

// Problem constants
#define NB     64
#define DIM    64
#define HW     1024
#define NTOK   65536         // NB*HW
#define KCODES 1024
#define ZQ_ELEMS 4194304     // NB*DIM*HW
#define CHUNK  64            // codes per smem chunk
#define NCHUNKS (KCODES / CHUNK)   // 16
#define EPS    0.02f

// ---------------------------------------------------------------------------
// Device global scratch (no allocation allowed)
// Fragment-ordered codebook: [chunk][n8][kstep][lane] -> uint2 {reg0, reg1}
//   reg0 = bf16x2 dims (2*t4, 2*t4+1), reg1 = dims (2*t4+8, 2*t4+9)
//   lane = g*4 + t4, code = chunk*64 + n8*8 + g, kstep selects dims [16k,16k+16)
// ---------------------------------------------------------------------------
__device__ __align__(16) uint2 g_cbf_hi[NCHUNKS * 8 * 4 * 32];  // 128 KB
__device__ __align__(16) uint2 g_cbf_lo[NCHUNKS * 8 * 4 * 32];  // 128 KB
__device__ float g_cnorm[KCODES];
__device__ int   g_idx[NTOK];
__device__ int   g_rescue[NTOK];
__device__ int   g_rescue_cnt;
__device__ float g_losssum;
__device__ int   g_hist[KCODES];

// ---------------------------------------------------------------------------
// Helpers
// ---------------------------------------------------------------------------
__device__ __forceinline__ void mma16816(float* c, const uint32_t* a,
                                         uint32_t b0, uint32_t b1) {
    asm volatile(
        "mma.sync.aligned.m16n8k16.row.col.f32.bf16.bf16.f32 "
        "{%0,%1,%2,%3}, {%4,%5,%6,%7}, {%8,%9}, {%0,%1,%2,%3};"
        : "+f"(c[0]), "+f"(c[1]), "+f"(c[2]), "+f"(c[3])
        : "r"(a[0]), "r"(a[1]), "r"(a[2]), "r"(a[3]), "r"(b0), "r"(b1));
}
__device__ __forceinline__ void split_pack(float v0, float v1,
                                           uint32_t& h, uint32_t& l) {
    __nv_bfloat16 h0 = __float2bfloat16_rn(v0);
    __nv_bfloat16 h1 = __float2bfloat16_rn(v1);
    __nv_bfloat16 l0 = __float2bfloat16_rn(v0 - __bfloat162float(h0));
    __nv_bfloat16 l1 = __float2bfloat16_rn(v1 - __bfloat162float(h1));
    h = ((uint32_t)__bfloat16_as_ushort(h1) << 16) | __bfloat16_as_ushort(h0);
    l = ((uint32_t)__bfloat16_as_ushort(l1) << 16) | __bfloat16_as_ushort(l0);
}
__device__ __forceinline__ uint32_t smem_u32(const void* p) {
    uint32_t a;
    asm("{ .reg .u64 t; cvta.to.shared.u64 t, %1; cvt.u32.u64 %0, t; }"
        : "=r"(a) : "l"(p));
    return a;
}
__device__ __forceinline__ void cp16(uint32_t dst, const void* src) {
    asm volatile("cp.async.cg.shared.global [%0], [%1], 16;"
                 :: "r"(dst), "l"(src));
}
#define CP_COMMIT() asm volatile("cp.async.commit_group;" ::: "memory")
#define CP_WAIT0()  asm volatile("cp.async.wait_group 0;" ::: "memory")

// top-2 tracker
__device__ __forceinline__ void upd(float s, int code, float& best, float& sec, int& idx) {
    if (s < best) { sec = best; best = s; idx = code; }
    else if (s < sec) { sec = s; }
}

// ---------------------------------------------------------------------------
// Prep: fragment-ordered bf16 hi/lo codebook, ||c||^2, zero counters
// ---------------------------------------------------------------------------
__global__ void prep_kernel(const float* __restrict__ cb) {
    int k = blockIdx.x * blockDim.x + threadIdx.x;
    if (k >= KCODES) return;
    float v[DIM];
    float s = 0.f;
#pragma unroll
    for (int c = 0; c < DIM; ++c) {
        v[c] = cb[k * DIM + c];
        s = fmaf(v[c], v[c], s);
    }
    g_cnorm[k] = s;
    g_hist[k]  = 0;
    if (k == 0) { g_losssum = 0.f; g_rescue_cnt = 0; }

    const int chunk = k >> 6;
    const int kc    = k & 63;
    const int n8    = kc >> 3;
    const int g     = kc & 7;
#pragma unroll
    for (int ks = 0; ks < 4; ++ks) {
#pragma unroll
        for (int t4 = 0; t4 < 4; ++t4) {
            int d0 = ks * 16 + t4 * 2;
            uint32_t h0, l0, h1, l1;
            split_pack(v[d0],     v[d0 + 1], h0, l0);
            split_pack(v[d0 + 8], v[d0 + 9], h1, l1);
            int idx = ((chunk * 8 + n8) * 4 + ks) * 32 + g * 4 + t4;
            g_cbf_hi[idx] = make_uint2(h0, h1);
            g_cbf_lo[idx] = make_uint2(l0, l1);
        }
    }
}

// ---------------------------------------------------------------------------
// HMMA argmin: 8 warps x 16 tokens, split-bf16 3-term mma.sync, margin flag
// smem: cn[1024] floats (4KB) + 2 chunk buffers of (hi 8KB + lo 8KB)
// ---------------------------------------------------------------------------
#define SMCN_F   0
#define SMBUF(b) (4096 + (b) * 16384)
#define SM_BYTES (4096 + 2 * 16384)

__global__ void __launch_bounds__(256) argmin_mma_kernel(const float* __restrict__ z) {
    __shared__ __align__(16) char smem[SM_BYTES];
    const uint32_t smb = smem_u32(smem);
    const int tid  = threadIdx.x;
    const int wid  = tid >> 5;
    const int lane = tid & 31;
    const int g    = lane >> 2;
    const int t4   = lane & 3;

    // cn -> smem (1024 floats, float4 per thread)
    {
        float4* dst = (float4*)(smem + SMCN_F);
        const float4* src = (const float4*)g_cnorm;
        dst[tid] = src[tid];
    }

    // A fragments: 16 tokens per warp, rows g and g+8
    const int wbase = blockIdx.x * 128 + wid * 16;
    const int b     = wbase >> 10;
    const int hw0   = (wbase & (HW - 1)) + g;      // token row g
    const float* zb = z + b * (DIM * HW);
    uint32_t Ah[16], Al[16];
#pragma unroll
    for (int ks = 0; ks < 4; ++ks) {
        int c0 = ks * 16 + t4 * 2;
        float t0a = zb[(c0)     * HW + hw0],     t0b = zb[(c0 + 1) * HW + hw0];
        float t1a = zb[(c0)     * HW + hw0 + 8], t1b = zb[(c0 + 1) * HW + hw0 + 8];
        float t0c = zb[(c0 + 8) * HW + hw0],     t0d = zb[(c0 + 9) * HW + hw0];
        float t1c = zb[(c0 + 8) * HW + hw0 + 8], t1d = zb[(c0 + 9) * HW + hw0 + 8];
        split_pack(t0a, t0b, Ah[ks * 4 + 0], Al[ks * 4 + 0]);
        split_pack(t1a, t1b, Ah[ks * 4 + 1], Al[ks * 4 + 1]);
        split_pack(t0c, t0d, Ah[ks * 4 + 2], Al[ks * 4 + 2]);
        split_pack(t1c, t1d, Ah[ks * 4 + 3], Al[ks * 4 + 3]);
    }

    // Prefetch chunk 0 (hi 8KB + lo 8KB): 1024 x 16B over 256 threads
    {
        const char* sh = (const char*)g_cbf_hi;
        const char* sl = (const char*)g_cbf_lo;
        uint32_t d = smb + SMBUF(0);
#pragma unroll
        for (int i = 0; i < 2; ++i) {
            cp16(d + tid * 16 + i * 4096,        sh + tid * 16 + i * 4096);
            cp16(d + 8192 + tid * 16 + i * 4096, sl + tid * 16 + i * 4096);
        }
        CP_COMMIT();
    }

    float best0 = 3.4e38f, sec0 = 3.4e38f; int idx0 = 0;
    float best1 = 3.4e38f, sec1 = 3.4e38f; int idx1 = 0;

    for (int t = 0; t < NCHUNKS; ++t) {
        const int buf = t & 1;
        CP_WAIT0();
        __syncthreads();                    // chunk t ready; prev compute done

        if (t + 1 < NCHUNKS) {              // prefetch t+1 into other buffer
            const char* sh = (const char*)g_cbf_hi + (t + 1) * 8192;
            const char* sl = (const char*)g_cbf_lo + (t + 1) * 8192;
            uint32_t d = smb + SMBUF(1 - buf);
#pragma unroll
            for (int i = 0; i < 2; ++i) {
                cp16(d + tid * 16 + i * 4096,        sh + tid * 16 + i * 4096);
                cp16(d + 8192 + tid * 16 + i * 4096, sl + tid * 16 + i * 4096);
            }
            CP_COMMIT();
        }

        const uint2* bh = (const uint2*)(smem + SMBUF(buf));
        const uint2* bl = bh + 1024;        // lo half (8KB)
        const float* cn = (const float*)(smem + SMCN_F);

#pragma unroll
        for (int n8 = 0; n8 < 8; ++n8) {
            float acc[4] = {0.f, 0.f, 0.f, 0.f};
#pragma unroll
            for (int ks = 0; ks < 4; ++ks) {
                uint2 Bh = bh[(n8 * 4 + ks) * 32 + lane];
                uint2 Bl = bl[(n8 * 4 + ks) * 32 + lane];
                mma16816(acc, &Ah[ks * 4], Bh.x, Bh.y);   // zh . ch
                mma16816(acc, &Ah[ks * 4], Bl.x, Bl.y);   // zh . cl
                mma16816(acc, &Al[ks * 4], Bh.x, Bh.y);   // zl . ch
            }
            const int code = t * CHUNK + n8 * 8 + t4 * 2;
            float2 cnv = *(const float2*)(cn + code);
            float s;
            s = fmaf(-2.f, acc[0], cnv.x); upd(s, code,     best0, sec0, idx0); // tok g
            s = fmaf(-2.f, acc[1], cnv.y); upd(s, code + 1, best0, sec0, idx0);
            s = fmaf(-2.f, acc[2], cnv.x); upd(s, code,     best1, sec1, idx1); // tok g+8
            s = fmaf(-2.f, acc[3], cnv.y); upd(s, code + 1, best1, sec1, idx1);
        }
        __syncthreads();                    // done reading buf before overwrite
    }

    // Reduce top-2 across the 4 lanes of each quad (same tokens, lane = g*4+t4)
#pragma unroll
    for (int off = 1; off <= 2; off <<= 1) {
        float ob, os; int oi;
        ob = __shfl_xor_sync(0xffffffffu, best0, off);
        os = __shfl_xor_sync(0xffffffffu, sec0,  off);
        oi = __shfl_xor_sync(0xffffffffu, idx0,  off);
        if (ob < best0 || (ob == best0 && oi < idx0)) { sec0 = fminf(best0, os); best0 = ob; idx0 = oi; }
        else                                          { sec0 = fminf(ob, sec0); }
        ob = __shfl_xor_sync(0xffffffffu, best1, off);
        os = __shfl_xor_sync(0xffffffffu, sec1,  off);
        oi = __shfl_xor_sync(0xffffffffu, idx1,  off);
        if (ob < best1 || (ob == best1 && oi < idx1)) { sec1 = fminf(best1, os); best1 = ob; idx1 = oi; }
        else                                          { sec1 = fminf(ob, sec1); }
    }

    if (t4 == 0) {
        const int tok0 = wbase + g;
        const int tok1 = wbase + g + 8;
        g_idx[tok0] = idx0;
        g_idx[tok1] = idx1;
        if (sec0 - best0 < EPS) { int s = atomicAdd(&g_rescue_cnt, 1); g_rescue[s] = tok0; }
        if (sec1 - best1 < EPS) { int s = atomicAdd(&g_rescue_cnt, 1); g_rescue[s] = tok1; }
    }
}

// ---------------------------------------------------------------------------
// Rescue: exact fp32 argmin for flagged tokens (one warp per token)
// ---------------------------------------------------------------------------
__global__ void __launch_bounds__(128) rescue_kernel(const float* __restrict__ z,
                                                     const float* __restrict__ cb) {
    const int nrs  = g_rescue_cnt;
    const int lane = threadIdx.x & 31;
    const int wpb  = blockDim.x >> 5;
    for (int i = blockIdx.x * wpb + (threadIdx.x >> 5); i < nrs; i += gridDim.x * wpb) {
        const int tok = g_rescue[i];
        const int b   = tok >> 10;
        const int hw  = tok & (HW - 1);
        const float* zp = z + b * (DIM * HW) + hw;
        float zr[DIM];
#pragma unroll
        for (int c = 0; c < DIM; ++c) zr[c] = zp[c << 10];

        float best = 3.4e38f; int bidx = 0x7fffffff;
        for (int k = lane; k < KCODES; k += 32) {
            const float4* cr = (const float4*)(cb + k * DIM);
            float a = 0.f;
#pragma unroll
            for (int c4 = 0; c4 < 16; ++c4) {
                float4 v = cr[c4];
                a = fmaf(zr[4 * c4 + 0], v.x, a);
                a = fmaf(zr[4 * c4 + 1], v.y, a);
                a = fmaf(zr[4 * c4 + 2], v.z, a);
                a = fmaf(zr[4 * c4 + 3], v.w, a);
            }
            float s = fmaf(-2.f, a, g_cnorm[k]);
            if (s < best) { best = s; bidx = k; }
        }
#pragma unroll
        for (int o = 16; o > 0; o >>= 1) {
            float ob = __shfl_down_sync(0xffffffffu, best, o);
            int   oi = __shfl_down_sync(0xffffffffu, bidx, o);
            if (ob < best || (ob == best && oi < bidx)) { best = ob; bidx = oi; }
        }
        if (lane == 0) g_idx[tok] = bidx;
    }
}

// ---------------------------------------------------------------------------
// Epilogue: gather -> NCHW out, loss partial, histogram
// ---------------------------------------------------------------------------
__global__ void __launch_bounds__(256) epilogue_kernel(const float* __restrict__ z,
                                                       const float* __restrict__ cb,
                                                       float* __restrict__ out) {
    const int b   = blockIdx.x >> 2;
    const int hw  = ((blockIdx.x & 3) << 8) | threadIdx.x;
    const int n   = (b << 10) | hw;
    const int idx = g_idx[n];
    atomicAdd(&g_hist[idx], 1);
    const float* cbr = cb + idx * DIM;
    const int base = b * (DIM * HW) + hw;

    float acc = 0.f;
#pragma unroll
    for (int c = 0; c < DIM; ++c) {
        float q  = __ldg(cbr + c);
        float zv = z[base + (c << 10)];
        float d  = q - zv;
        acc = fmaf(d, d, acc);
        out[base + (c << 10)] = q;
    }
#pragma unroll
    for (int o = 16; o > 0; o >>= 1)
        acc += __shfl_down_sync(0xffffffffu, acc, o);
    __shared__ float red[8];
    if ((threadIdx.x & 31) == 0) red[threadIdx.x >> 5] = acc;
    __syncthreads();
    if (threadIdx.x == 0) {
        float s = 0.f;
#pragma unroll
        for (int w = 0; w < 8; ++w) s += red[w];
        atomicAdd(&g_losssum, s);
    }
}

// ---------------------------------------------------------------------------
// Finalize: perplexity + loss scalars
// ---------------------------------------------------------------------------
__global__ void finalize_kernel(const int* __restrict__ flg,
                                float* __restrict__ out, int write_scalars) {
    const int k = threadIdx.x;
    float e = (float)g_hist[k] * (1.f / (float)NTOK);
    float t = e * logf(e + 1e-10f);
#pragma unroll
    for (int o = 16; o > 0; o >>= 1)
        t += __shfl_down_sync(0xffffffffu, t, o);
    __shared__ float red[32];
    if ((k & 31) == 0) red[k >> 5] = t;
    __syncthreads();
    if (k < 32) {
        float v = red[k];
#pragma unroll
        for (int o = 16; o > 0; o >>= 1)
            v += __shfl_down_sync(0xffffffffu, v, o);
        if (k == 0 && write_scalars) {
            int fbits = *flg;
            float loss = (fbits != 0)
                       ? 1.25f * g_losssum * (1.f / (float)ZQ_ELEMS)
                       : 0.f;
            out[ZQ_ELEMS]     = loss;
            out[ZQ_ELEMS + 1] = expf(-v);
        }
    }
}

// ---------------------------------------------------------------------------
extern "C" void kernel_launch(void* const* d_in, const int* in_sizes, int n_in,
                              void* d_out, int out_size) {
    const float* z   = (const float*)d_in[0];
    const float* cb  = (const float*)d_in[1];
    const int*   flg = (const int*)d_in[3];
    float* out = (float*)d_out;

    prep_kernel<<<8, 128>>>(cb);
    argmin_mma_kernel<<<NTOK / 128, 256>>>(z);
    rescue_kernel<<<64, 128>>>(z, cb);
    epilogue_kernel<<<256, 256>>>(z, cb, out);
    finalize_kernel<<<1, 1024>>>(flg, out, out_size >= ZQ_ELEMS + 2 ? 1 : 0);
}

// round 7
// speedup vs baseline: 1.6438x; 1.0631x over previous
#include <cuda_runtime.h>
#include <cuda_bf16.h>
#include <math.h>
#include <stdint.h>

// Problem constants
#define NB     64
#define DIM    64
#define HW     1024
#define NTOK   65536         // NB*HW
#define KCODES 1024
#define ZQ_ELEMS 4194304     // NB*DIM*HW
#define CHUNK  64            // codes per smem chunk
#define NCHUNKS (KCODES / CHUNK)   // 16
#define EPS    0.02f

// ---------------------------------------------------------------------------
// Device global scratch (no allocation allowed)
// Fragment-ordered codebook: [chunk][n8][kstep][lane] -> uint2 {reg0, reg1}
// ---------------------------------------------------------------------------
__device__ __align__(16) uint2 g_cbf_hi[NCHUNKS * 8 * 4 * 32];  // 128 KB
__device__ __align__(16) uint2 g_cbf_lo[NCHUNKS * 8 * 4 * 32];  // 128 KB
__device__ float g_cnorm[KCODES];
__device__ int   g_idx[NTOK];
__device__ int   g_rescue[NTOK];
__device__ int   g_rescue_cnt;
__device__ float g_losssum;
__device__ int   g_hist[KCODES];

// ---------------------------------------------------------------------------
// Helpers
// ---------------------------------------------------------------------------
__device__ __forceinline__ void mma16816(float* c, const uint32_t* a,
                                         uint32_t b0, uint32_t b1) {
    asm volatile(
        "mma.sync.aligned.m16n8k16.row.col.f32.bf16.bf16.f32 "
        "{%0,%1,%2,%3}, {%4,%5,%6,%7}, {%8,%9}, {%0,%1,%2,%3};"
        : "+f"(c[0]), "+f"(c[1]), "+f"(c[2]), "+f"(c[3])
        : "r"(a[0]), "r"(a[1]), "r"(a[2]), "r"(a[3]), "r"(b0), "r"(b1));
}
__device__ __forceinline__ void split_pack(float v0, float v1,
                                           uint32_t& h, uint32_t& l) {
    __nv_bfloat16 h0 = __float2bfloat16_rn(v0);
    __nv_bfloat16 h1 = __float2bfloat16_rn(v1);
    __nv_bfloat16 l0 = __float2bfloat16_rn(v0 - __bfloat162float(h0));
    __nv_bfloat16 l1 = __float2bfloat16_rn(v1 - __bfloat162float(h1));
    h = ((uint32_t)__bfloat16_as_ushort(h1) << 16) | __bfloat16_as_ushort(h0);
    l = ((uint32_t)__bfloat16_as_ushort(l1) << 16) | __bfloat16_as_ushort(l0);
}
__device__ __forceinline__ uint32_t smem_u32(const void* p) {
    uint32_t a;
    asm("{ .reg .u64 t; cvta.to.shared.u64 t, %1; cvt.u32.u64 %0, t; }"
        : "=r"(a) : "l"(p));
    return a;
}
__device__ __forceinline__ void cp16(uint32_t dst, const void* src) {
    asm volatile("cp.async.cg.shared.global [%0], [%1], 16;"
                 :: "r"(dst), "l"(src));
}
#define CP_COMMIT() asm volatile("cp.async.commit_group;" ::: "memory")
#define CP_WAIT0()  asm volatile("cp.async.wait_group 0;" ::: "memory")

// top-2 tracker
__device__ __forceinline__ void upd(float s, int code, float& best, float& sec, int& idx) {
    if (s < best) { sec = best; best = s; idx = code; }
    else if (s < sec) { sec = s; }
}

// ---------------------------------------------------------------------------
// Prep: fragment-ordered bf16 hi/lo codebook, ||c||^2, zero counters
// ---------------------------------------------------------------------------
__global__ void prep_kernel(const float* __restrict__ cb) {
    int k = blockIdx.x * blockDim.x + threadIdx.x;
    if (k >= KCODES) return;
    float v[DIM];
    float s = 0.f;
#pragma unroll
    for (int c = 0; c < DIM; ++c) {
        v[c] = cb[k * DIM + c];
        s = fmaf(v[c], v[c], s);
    }
    g_cnorm[k] = s;
    g_hist[k]  = 0;
    if (k == 0) { g_losssum = 0.f; g_rescue_cnt = 0; }

    const int chunk = k >> 6;
    const int kc    = k & 63;
    const int n8    = kc >> 3;
    const int g     = kc & 7;
#pragma unroll
    for (int ks = 0; ks < 4; ++ks) {
#pragma unroll
        for (int t4 = 0; t4 < 4; ++t4) {
            int d0 = ks * 16 + t4 * 2;
            uint32_t h0, l0, h1, l1;
            split_pack(v[d0],     v[d0 + 1], h0, l0);
            split_pack(v[d0 + 8], v[d0 + 9], h1, l1);
            int idx = ((chunk * 8 + n8) * 4 + ks) * 32 + g * 4 + t4;
            g_cbf_hi[idx] = make_uint2(h0, h1);
            g_cbf_lo[idx] = make_uint2(l0, l1);
        }
    }
}

// ---------------------------------------------------------------------------
// HMMA argmin: 8 warps x 16 tokens; split-bf16 3-term mma.sync with
// 2 independent accumulator chains per n8 (hh: len 4, cc: len 8) -> 16
// concurrent tensor chains per warp. B fragments hoisted per n8.
// ---------------------------------------------------------------------------
#define SMCN_F   0
#define SMBUF(b) (4096 + (b) * 16384)
#define SM_BYTES (4096 + 2 * 16384)

__global__ void __launch_bounds__(256) argmin_mma_kernel(const float* __restrict__ z) {
    __shared__ __align__(16) char smem[SM_BYTES];
    const uint32_t smb = smem_u32(smem);
    const int tid  = threadIdx.x;
    const int wid  = tid >> 5;
    const int lane = tid & 31;
    const int g    = lane >> 2;
    const int t4   = lane & 3;

    // cn -> smem (1024 floats, float4 per thread)
    {
        float4* dst = (float4*)(smem + SMCN_F);
        const float4* src = (const float4*)g_cnorm;
        dst[tid] = src[tid];
    }

    // A fragments: 16 tokens per warp, rows g and g+8
    const int wbase = blockIdx.x * 128 + wid * 16;
    const int b     = wbase >> 10;
    const int hw0   = (wbase & (HW - 1)) + g;
    const float* zb = z + b * (DIM * HW);
    uint32_t Ah[16], Al[16];
#pragma unroll
    for (int ks = 0; ks < 4; ++ks) {
        int c0 = ks * 16 + t4 * 2;
        float t0a = zb[(c0)     * HW + hw0],     t0b = zb[(c0 + 1) * HW + hw0];
        float t1a = zb[(c0)     * HW + hw0 + 8], t1b = zb[(c0 + 1) * HW + hw0 + 8];
        float t0c = zb[(c0 + 8) * HW + hw0],     t0d = zb[(c0 + 9) * HW + hw0];
        float t1c = zb[(c0 + 8) * HW + hw0 + 8], t1d = zb[(c0 + 9) * HW + hw0 + 8];
        split_pack(t0a, t0b, Ah[ks * 4 + 0], Al[ks * 4 + 0]);
        split_pack(t1a, t1b, Ah[ks * 4 + 1], Al[ks * 4 + 1]);
        split_pack(t0c, t0d, Ah[ks * 4 + 2], Al[ks * 4 + 2]);
        split_pack(t1c, t1d, Ah[ks * 4 + 3], Al[ks * 4 + 3]);
    }

    // Prefetch chunk 0 (hi 8KB + lo 8KB)
    {
        const char* sh = (const char*)g_cbf_hi;
        const char* sl = (const char*)g_cbf_lo;
        uint32_t d = smb + SMBUF(0);
#pragma unroll
        for (int i = 0; i < 2; ++i) {
            cp16(d + tid * 16 + i * 4096,        sh + tid * 16 + i * 4096);
            cp16(d + 8192 + tid * 16 + i * 4096, sl + tid * 16 + i * 4096);
        }
        CP_COMMIT();
    }

    float best0 = 3.4e38f, sec0 = 3.4e38f; int idx0 = 0;
    float best1 = 3.4e38f, sec1 = 3.4e38f; int idx1 = 0;

    for (int t = 0; t < NCHUNKS; ++t) {
        const int buf = t & 1;
        CP_WAIT0();
        __syncthreads();

        if (t + 1 < NCHUNKS) {
            const char* sh = (const char*)g_cbf_hi + (t + 1) * 8192;
            const char* sl = (const char*)g_cbf_lo + (t + 1) * 8192;
            uint32_t d = smb + SMBUF(1 - buf);
#pragma unroll
            for (int i = 0; i < 2; ++i) {
                cp16(d + tid * 16 + i * 4096,        sh + tid * 16 + i * 4096);
                cp16(d + 8192 + tid * 16 + i * 4096, sl + tid * 16 + i * 4096);
            }
            CP_COMMIT();
        }

        const uint2* bh = (const uint2*)(smem + SMBUF(buf));
        const uint2* bl = bh + 1024;
        const float* cn = (const float*)(smem + SMCN_F);

#pragma unroll
        for (int n8 = 0; n8 < 8; ++n8) {
            // Hoisted B fragments for all 4 K-steps
            uint2 Bh[4], Bl[4];
#pragma unroll
            for (int ks = 0; ks < 4; ++ks) {
                Bh[ks] = bh[(n8 * 4 + ks) * 32 + lane];
                Bl[ks] = bl[(n8 * 4 + ks) * 32 + lane];
            }
            // Two independent accumulator chains: hh (len 4), cc (len 8)
            float hh[4] = {0.f, 0.f, 0.f, 0.f};
            float cc[4] = {0.f, 0.f, 0.f, 0.f};
#pragma unroll
            for (int ks = 0; ks < 4; ++ks) {
                mma16816(hh, &Ah[ks * 4], Bh[ks].x, Bh[ks].y);  // zh.ch
                mma16816(cc, &Ah[ks * 4], Bl[ks].x, Bl[ks].y);  // zh.cl
                mma16816(cc, &Al[ks * 4], Bh[ks].x, Bh[ks].y);  // zl.ch
            }
            const int code = t * CHUNK + n8 * 8 + t4 * 2;
            float2 cnv = *(const float2*)(cn + code);
            float s;
            s = fmaf(-2.f, hh[0] + cc[0], cnv.x); upd(s, code,     best0, sec0, idx0);
            s = fmaf(-2.f, hh[1] + cc[1], cnv.y); upd(s, code + 1, best0, sec0, idx0);
            s = fmaf(-2.f, hh[2] + cc[2], cnv.x); upd(s, code,     best1, sec1, idx1);
            s = fmaf(-2.f, hh[3] + cc[3], cnv.y); upd(s, code + 1, best1, sec1, idx1);
        }
        __syncthreads();
    }

    // Reduce top-2 across the 4 lanes of each quad
#pragma unroll
    for (int off = 1; off <= 2; off <<= 1) {
        float ob, os; int oi;
        ob = __shfl_xor_sync(0xffffffffu, best0, off);
        os = __shfl_xor_sync(0xffffffffu, sec0,  off);
        oi = __shfl_xor_sync(0xffffffffu, idx0,  off);
        if (ob < best0 || (ob == best0 && oi < idx0)) { sec0 = fminf(best0, os); best0 = ob; idx0 = oi; }
        else                                          { sec0 = fminf(ob, sec0); }
        ob = __shfl_xor_sync(0xffffffffu, best1, off);
        os = __shfl_xor_sync(0xffffffffu, sec1,  off);
        oi = __shfl_xor_sync(0xffffffffu, idx1,  off);
        if (ob < best1 || (ob == best1 && oi < idx1)) { sec1 = fminf(best1, os); best1 = ob; idx1 = oi; }
        else                                          { sec1 = fminf(ob, sec1); }
    }

    if (t4 == 0) {
        const int tok0 = wbase + g;
        const int tok1 = wbase + g + 8;
        g_idx[tok0] = idx0;
        g_idx[tok1] = idx1;
        if (sec0 - best0 < EPS) { int s = atomicAdd(&g_rescue_cnt, 1); g_rescue[s] = tok0; }
        if (sec1 - best1 < EPS) { int s = atomicAdd(&g_rescue_cnt, 1); g_rescue[s] = tok1; }
    }
}

// ---------------------------------------------------------------------------
// Rescue: exact fp32 argmin for flagged tokens (one warp per token)
// ---------------------------------------------------------------------------
__global__ void __launch_bounds__(128) rescue_kernel(const float* __restrict__ z,
                                                     const float* __restrict__ cb) {
    const int nrs  = g_rescue_cnt;
    const int lane = threadIdx.x & 31;
    const int wpb  = blockDim.x >> 5;
    for (int i = blockIdx.x * wpb + (threadIdx.x >> 5); i < nrs; i += gridDim.x * wpb) {
        const int tok = g_rescue[i];
        const int b   = tok >> 10;
        const int hw  = tok & (HW - 1);
        const float* zp = z + b * (DIM * HW) + hw;
        float zr[DIM];
#pragma unroll
        for (int c = 0; c < DIM; ++c) zr[c] = zp[c << 10];

        float best = 3.4e38f; int bidx = 0x7fffffff;
        for (int k = lane; k < KCODES; k += 32) {
            const float4* cr = (const float4*)(cb + k * DIM);
            float a = 0.f;
#pragma unroll
            for (int c4 = 0; c4 < 16; ++c4) {
                float4 v = cr[c4];
                a = fmaf(zr[4 * c4 + 0], v.x, a);
                a = fmaf(zr[4 * c4 + 1], v.y, a);
                a = fmaf(zr[4 * c4 + 2], v.z, a);
                a = fmaf(zr[4 * c4 + 3], v.w, a);
            }
            float s = fmaf(-2.f, a, g_cnorm[k]);
            if (s < best) { best = s; bidx = k; }
        }
#pragma unroll
        for (int o = 16; o > 0; o >>= 1) {
            float ob = __shfl_down_sync(0xffffffffu, best, o);
            int   oi = __shfl_down_sync(0xffffffffu, bidx, o);
            if (ob < best || (ob == best && oi < bidx)) { best = ob; bidx = oi; }
        }
        if (lane == 0) g_idx[tok] = bidx;
    }
}

// ---------------------------------------------------------------------------
// Epilogue: gather -> NCHW out (float4 codebook reads), loss, histogram
// grid 512 x 128 for occupancy
// ---------------------------------------------------------------------------
__global__ void __launch_bounds__(128) epilogue_kernel(const float* __restrict__ z,
                                                       const float* __restrict__ cb,
                                                       float* __restrict__ out) {
    const int n   = blockIdx.x * 128 + threadIdx.x;   // consecutive hw -> coalesced
    const int b   = n >> 10;
    const int hw  = n & (HW - 1);
    const int idx = g_idx[n];
    atomicAdd(&g_hist[idx], 1);
    const float4* cbr = (const float4*)(cb + idx * DIM);
    const int base = b * (DIM * HW) + hw;

    float acc = 0.f;
#pragma unroll
    for (int c4 = 0; c4 < 16; ++c4) {
        float4 q = __ldg(cbr + c4);
        const int c = c4 * 4;
        float z0 = z[base + ((c + 0) << 10)];
        float z1 = z[base + ((c + 1) << 10)];
        float z2 = z[base + ((c + 2) << 10)];
        float z3 = z[base + ((c + 3) << 10)];
        float d0 = q.x - z0, d1 = q.y - z1, d2 = q.z - z2, d3 = q.w - z3;
        acc = fmaf(d0, d0, acc);
        acc = fmaf(d1, d1, acc);
        acc = fmaf(d2, d2, acc);
        acc = fmaf(d3, d3, acc);
        out[base + ((c + 0) << 10)] = q.x;
        out[base + ((c + 1) << 10)] = q.y;
        out[base + ((c + 2) << 10)] = q.z;
        out[base + ((c + 3) << 10)] = q.w;
    }
#pragma unroll
    for (int o = 16; o > 0; o >>= 1)
        acc += __shfl_down_sync(0xffffffffu, acc, o);
    __shared__ float red[4];
    if ((threadIdx.x & 31) == 0) red[threadIdx.x >> 5] = acc;
    __syncthreads();
    if (threadIdx.x == 0) {
        float s = red[0] + red[1] + red[2] + red[3];
        atomicAdd(&g_losssum, s);
    }
}

// ---------------------------------------------------------------------------
// Finalize: perplexity + loss scalars
// ---------------------------------------------------------------------------
__global__ void finalize_kernel(const int* __restrict__ flg,
                                float* __restrict__ out, int write_scalars) {
    const int k = threadIdx.x;
    float e = (float)g_hist[k] * (1.f / (float)NTOK);
    float t = e * logf(e + 1e-10f);
#pragma unroll
    for (int o = 16; o > 0; o >>= 1)
        t += __shfl_down_sync(0xffffffffu, t, o);
    __shared__ float red[32];
    if ((k & 31) == 0) red[k >> 5] = t;
    __syncthreads();
    if (k < 32) {
        float v = red[k];
#pragma unroll
        for (int o = 16; o > 0; o >>= 1)
            v += __shfl_down_sync(0xffffffffu, v, o);
        if (k == 0 && write_scalars) {
            int fbits = *flg;
            float loss = (fbits != 0)
                       ? 1.25f * g_losssum * (1.f / (float)ZQ_ELEMS)
                       : 0.f;
            out[ZQ_ELEMS]     = loss;
            out[ZQ_ELEMS + 1] = expf(-v);
        }
    }
}

// ---------------------------------------------------------------------------
extern "C" void kernel_launch(void* const* d_in, const int* in_sizes, int n_in,
                              void* d_out, int out_size) {
    const float* z   = (const float*)d_in[0];
    const float* cb  = (const float*)d_in[1];
    const int*   flg = (const int*)d_in[3];
    float* out = (float*)d_out;

    prep_kernel<<<8, 128>>>(cb);
    argmin_mma_kernel<<<NTOK / 128, 256>>>(z);
    rescue_kernel<<<64, 128>>>(z, cb);
    epilogue_kernel<<<NTOK / 128, 128>>>(z, cb, out);
    finalize_kernel<<<1, 1024>>>(flg, out, out_size >= ZQ_ELEMS + 2 ? 1 : 0);
}